// round 6
// baseline (speedup 1.0000x reference)
#include <cuda_runtime.h>

#define D       1024
#define BATCH   64
#define KSPLIT  16
#define KSLICE  (D / KSPLIT)     // 64
#define NTILE_W 128
#define NTILES  (D / NTILE_W)    // 8
#define LOG2E   1.4426950408889634f
#define LN2     0.6931471805599453f

// ---------------- scratch (no allocations allowed) ----------------
__device__ __align__(16) float g_xl[BATCH * D];
__device__ __align__(16) float g_bl[BATCH * D];
__device__ __align__(16) float g_xs[BATCH * D];
__device__ __align__(16) float g_h1[BATCH * D];
__device__ __align__(16) float g_h2[BATCH * D];
__device__ __align__(16) float g_part[KSPLIT * BATCH * D];
__device__ unsigned g_cnt[2][NTILES];

__device__ __forceinline__ float ex2f(float x) {
    float r;
    asm("ex2.approx.ftz.f32 %0, %1;" : "=f"(r) : "f"(x));
    return r;
}

__device__ __forceinline__ void ffma2(unsigned long long& acc,
                                      unsigned long long a,
                                      unsigned long long b) {
    asm("fma.rn.f32x2 %0, %1, %2, %3;" : "=l"(acc) : "l"(a), "l"(b), "l"(acc));
}

__device__ __forceinline__ unsigned long long dup2(float v) {
    unsigned long long r;
    asm("mov.b64 %0, {%1, %1};" : "=l"(r) : "f"(v));
    return r;
}

// ---------------- kernel 1: per-row bitonic sort + prefix-sum Bsum ----------------
__global__ void __launch_bounds__(D) sort_kernel(const float* __restrict__ x) {
    int row = blockIdx.x;
    int tid = threadIdx.x;
    __shared__ __align__(16) float sv[D];
    __shared__ float wsum[32];

    sv[tid] = x[row * D + tid];
    __syncthreads();

    for (int k = 2; k <= D; k <<= 1) {
        for (int j = k >> 1; j > 0; j >>= 1) {
            int ixj = tid ^ j;
            if (ixj > tid) {
                float a = sv[tid], b = sv[ixj];
                bool up = ((tid & k) == 0);
                if ((a > b) == up) { sv[tid] = b; sv[ixj] = a; }
            }
            __syncthreads();
        }
    }

    float v = sv[tid];
    int lane = tid & 31, wid = tid >> 5;
    float p = v;
#pragma unroll
    for (int off = 1; off < 32; off <<= 1) {
        float n = __shfl_up_sync(0xffffffffu, p, off);
        if (lane >= off) p += n;
    }
    if (lane == 31) wsum[wid] = p;
    __syncthreads();
    if (wid == 0) {
        float w = wsum[lane];
#pragma unroll
        for (int off = 1; off < 32; off <<= 1) {
            float n = __shfl_up_sync(0xffffffffu, w, off);
            if (lane >= off) w += n;
        }
        wsum[lane] = w;
    }
    __syncthreads();
    float S    = wsum[31];
    float pinc = p + (wid ? wsum[wid - 1] : 0.f);
    float bs   = (float)(2 * tid - D) * v + S - 2.f * (pinc - v);
    g_xl[row * D + tid] = v * LOG2E;
    g_bl[row * D + tid] = bs * LOG2E;
}

// ---------------- kernel 2: windowed soft-sort, unroll-4 ----------------
__global__ void __launch_bounds__(256) softsort_kernel() {
    int row = blockIdx.y;
    int i   = blockIdx.x * blockDim.x + threadIdx.x;
    __shared__ __align__(16) float sxl[D];
    __shared__ __align__(16) float sbl[D];
    ((float4*)sxl)[threadIdx.x] = ((const float4*)(g_xl + row * D))[threadIdx.x];
    ((float4*)sbl)[threadIdx.x] = ((const float4*)(g_bl + row * D))[threadIdx.x];
    __syncthreads();

    float c  = (float)(D - 1 - 2 * i);
    int   rm = D - 1 - i;
    float mx = fmaf(c, sxl[rm], -sbl[rm]);
    float num = sxl[rm], den = 1.f;
    const float T = 22.f;

    {
        int r = rm - 1;
        for (; r >= 3; r -= 4) {
            float t0 = fmaf(c, sxl[r],     -sbl[r])     - mx;
            float t1 = fmaf(c, sxl[r - 1], -sbl[r - 1]) - mx;
            float t2 = fmaf(c, sxl[r - 2], -sbl[r - 2]) - mx;
            float t3 = fmaf(c, sxl[r - 3], -sbl[r - 3]) - mx;
            float e0 = ex2f(t0), e1 = ex2f(t1), e2 = ex2f(t2), e3 = ex2f(t3);
            den += e0; num = fmaf(e0, sxl[r],     num);
            den += e1; num = fmaf(e1, sxl[r - 1], num);
            den += e2; num = fmaf(e2, sxl[r - 2], num);
            den += e3; num = fmaf(e3, sxl[r - 3], num);
            if (t3 < -T) { r = -1; break; }
        }
        for (; r >= 0; --r) {
            float t = fmaf(c, sxl[r], -sbl[r]) - mx;
            if (t < -T) break;
            float e = ex2f(t);
            den += e; num = fmaf(e, sxl[r], num);
        }
    }
    {
        int r = rm + 1;
        for (; r < D - 3; r += 4) {
            float t0 = fmaf(c, sxl[r],     -sbl[r])     - mx;
            float t1 = fmaf(c, sxl[r + 1], -sbl[r + 1]) - mx;
            float t2 = fmaf(c, sxl[r + 2], -sbl[r + 2]) - mx;
            float t3 = fmaf(c, sxl[r + 3], -sbl[r + 3]) - mx;
            float e0 = ex2f(t0), e1 = ex2f(t1), e2 = ex2f(t2), e3 = ex2f(t3);
            den += e0; num = fmaf(e0, sxl[r],     num);
            den += e1; num = fmaf(e1, sxl[r + 1], num);
            den += e2; num = fmaf(e2, sxl[r + 2], num);
            den += e3; num = fmaf(e3, sxl[r + 3], num);
            if (t3 < -T) { r = D; break; }
        }
        for (; r < D; ++r) {
            float t = fmaf(c, sxl[r], -sbl[r]) - mx;
            if (t < -T) break;
            float e = ex2f(t);
            den += e; num = fmaf(e, sxl[r], num);
        }
    }
    g_xs[row * D + i] = num * LN2 / den;
}

// ---------------- kernel 3: split-K GEMM (64m x 128n tile, 4m x 8n/thread) ------
__global__ void __launch_bounds__(256) gemm_fused_kernel(int layer,
                                                         const float* __restrict__ W,
                                                         const float* __restrict__ bias) {
    const float* A = (layer == 0) ? g_xs : g_h1;
    float*       H = (layer == 0) ? g_h1 : g_h2;
    int nt  = blockIdx.x;
    int ks  = blockIdx.y;
    int tid = threadIdx.x;
    int tx  = tid & 15;            // n group of 8
    int ty  = tid >> 4;            // m group of 4

    __shared__ __align__(16) float As[2][16][68];    // [k][m] transposed
    __shared__ __align__(16) float Ws[2][16][132];   // [k][n]
    __shared__ int s_last;

    unsigned long long acc[2][8] = {};   // [m-pair][n]

    int m_a = tid >> 2;            // 0..63
    int k4a = (tid & 3) << 2;      // 0,4,8,12
    int n_w = tid >> 1;            // 0..127
    int k8w = (tid & 1) << 3;      // 0,8
    const int kbase = ks * KSLICE;

    {
        float4 av  = *(const float4*)&A[m_a * D + kbase + k4a];
        float4 wv0 = *(const float4*)&W[(nt * NTILE_W + n_w) * D + kbase + k8w];
        float4 wv1 = *(const float4*)&W[(nt * NTILE_W + n_w) * D + kbase + k8w + 4];
        As[0][k4a + 0][m_a] = av.x; As[0][k4a + 1][m_a] = av.y;
        As[0][k4a + 2][m_a] = av.z; As[0][k4a + 3][m_a] = av.w;
        Ws[0][k8w + 0][n_w] = wv0.x; Ws[0][k8w + 1][n_w] = wv0.y;
        Ws[0][k8w + 2][n_w] = wv0.z; Ws[0][k8w + 3][n_w] = wv0.w;
        Ws[0][k8w + 4][n_w] = wv1.x; Ws[0][k8w + 5][n_w] = wv1.y;
        Ws[0][k8w + 6][n_w] = wv1.z; Ws[0][k8w + 7][n_w] = wv1.w;
    }
    __syncthreads();

#pragma unroll
    for (int c = 0; c < 4; c++) {
        int buf = c & 1;
        float4 av2, wv2a, wv2b;
        if (c < 3) {
            int kb = kbase + (c + 1) * 16;
            av2  = *(const float4*)&A[m_a * D + kb + k4a];
            wv2a = *(const float4*)&W[(nt * NTILE_W + n_w) * D + kb + k8w];
            wv2b = *(const float4*)&W[(nt * NTILE_W + n_w) * D + kb + k8w + 4];
        }
#pragma unroll
        for (int k = 0; k < 16; k++) {
            ulonglong2 la = *(const ulonglong2*)&As[buf][k][ty * 4];   // (m0,m1),(m2,m3)
            float4 bv0 = *(const float4*)&Ws[buf][k][tx * 8];
            float4 bv1 = *(const float4*)&Ws[buf][k][tx * 8 + 4];
            unsigned long long b0 = dup2(bv0.x), b1 = dup2(bv0.y);
            unsigned long long b2 = dup2(bv0.z), b3 = dup2(bv0.w);
            unsigned long long b4 = dup2(bv1.x), b5 = dup2(bv1.y);
            unsigned long long b6 = dup2(bv1.z), b7 = dup2(bv1.w);
            ffma2(acc[0][0], la.x, b0); ffma2(acc[1][0], la.y, b0);
            ffma2(acc[0][1], la.x, b1); ffma2(acc[1][1], la.y, b1);
            ffma2(acc[0][2], la.x, b2); ffma2(acc[1][2], la.y, b2);
            ffma2(acc[0][3], la.x, b3); ffma2(acc[1][3], la.y, b3);
            ffma2(acc[0][4], la.x, b4); ffma2(acc[1][4], la.y, b4);
            ffma2(acc[0][5], la.x, b5); ffma2(acc[1][5], la.y, b5);
            ffma2(acc[0][6], la.x, b6); ffma2(acc[1][6], la.y, b6);
            ffma2(acc[0][7], la.x, b7); ffma2(acc[1][7], la.y, b7);
        }
        if (c < 3) {
            int nb = buf ^ 1;
            As[nb][k4a + 0][m_a] = av2.x; As[nb][k4a + 1][m_a] = av2.y;
            As[nb][k4a + 2][m_a] = av2.z; As[nb][k4a + 3][m_a] = av2.w;
            Ws[nb][k8w + 0][n_w] = wv2a.x; Ws[nb][k8w + 1][n_w] = wv2a.y;
            Ws[nb][k8w + 2][n_w] = wv2a.z; Ws[nb][k8w + 3][n_w] = wv2a.w;
            Ws[nb][k8w + 4][n_w] = wv2b.x; Ws[nb][k8w + 5][n_w] = wv2b.y;
            Ws[nb][k8w + 6][n_w] = wv2b.z; Ws[nb][k8w + 7][n_w] = wv2b.w;
            __syncthreads();
        }
    }

    // write partials: acc[p][j] lanes = (m = ty*4+2p, m+1), n = nt*128 + tx*8 + j
#pragma unroll
    for (int p = 0; p < 2; p++) {
        float lo[8], hi[8];
#pragma unroll
        for (int j = 0; j < 8; j++) {
            unsigned l, h;
            asm("mov.b64 {%0,%1}, %2;" : "=r"(l), "=r"(h) : "l"(acc[p][j]));
            lo[j] = __uint_as_float(l);
            hi[j] = __uint_as_float(h);
        }
        int m0 = ty * 4 + 2 * p;
        float* dst0 = &g_part[(ks * BATCH + m0)     * D + nt * NTILE_W + tx * 8];
        float* dst1 = &g_part[(ks * BATCH + m0 + 1) * D + nt * NTILE_W + tx * 8];
        *(float4*)dst0       = make_float4(lo[0], lo[1], lo[2], lo[3]);
        *(float4*)(dst0 + 4) = make_float4(lo[4], lo[5], lo[6], lo[7]);
        *(float4*)dst1       = make_float4(hi[0], hi[1], hi[2], hi[3]);
        *(float4*)(dst1 + 4) = make_float4(hi[4], hi[5], hi[6], hi[7]);
    }

    // ---- election: last block for this n-tile does the combine ----
    __syncthreads();
    __threadfence();
    if (tid == 0) {
        unsigned old = atomicAdd(&g_cnt[layer][nt], 1u);
        s_last = (old == KSPLIT - 1);
        if (s_last) g_cnt[layer][nt] = 0;
    }
    __syncthreads();
    if (!s_last) return;
    __threadfence();

    // combine: 64 rows x 32 float4-cols = 2048 float4, 8 per thread
#pragma unroll
    for (int t = 0; t < 8; t++) {
        int idx = t * 256 + tid;
        int m   = idx >> 5;
        int c4  = idx & 31;
        int col = nt * (NTILE_W / 4) + c4;
        int f4  = m * (D / 4) + col;
        float4 s = ((const float4*)g_part)[(0 * BATCH + m) * (D / 4) + col];
#pragma unroll
        for (int k = 1; k < KSPLIT; k++) {
            float4 v = ((const float4*)g_part)[(k * BATCH + m) * (D / 4) + col];
            s.x += v.x; s.y += v.y; s.z += v.z; s.w += v.w;
        }
        float4 bv = ((const float4*)bias)[col];
        s.x += bv.x; s.y += bv.y; s.z += bv.z; s.w += bv.w;
        s.x = (s.x >= 0.f) ? s.x : 0.01f * s.x;
        s.y = (s.y >= 0.f) ? s.y : 0.01f * s.y;
        s.z = (s.z >= 0.f) ? s.z : 0.01f * s.z;
        s.w = (s.w >= 0.f) ? s.w : 0.01f * s.w;
        ((float4*)H)[f4] = s;
    }
}

// ---------------- kernel 4: final 1024 -> 2 head ----------------
__global__ void __launch_bounds__(256) final_kernel(const float* __restrict__ W3,
                                                    const float* __restrict__ b3,
                                                    float* __restrict__ out) {
    int b   = blockIdx.x;
    int tid = threadIdx.x;
    int c   = tid >> 7;
    int j0  = tid & 127;
    float acc = 0.f;
#pragma unroll
    for (int t = 0; t < 8; t++) {
        int j = j0 + (t << 7);
        acc = fmaf(g_h2[b * D + j], W3[c * D + j], acc);
    }
    __shared__ float red[8];
#pragma unroll
    for (int off = 16; off; off >>= 1)
        acc += __shfl_down_sync(0xffffffffu, acc, off);
    if ((tid & 31) == 0) red[tid >> 5] = acc;
    __syncthreads();
    if (tid < 2) {
        float s = (red[tid * 4] + red[tid * 4 + 1]) +
                  (red[tid * 4 + 2] + red[tid * 4 + 3]);
        out[b * 2 + tid] = s + b3[tid];
    }
}

extern "C" void kernel_launch(void* const* d_in, const int* in_sizes, int n_in,
                              void* d_out, int out_size) {
    const float* x  = (const float*)d_in[0];
    const float* W1 = (const float*)d_in[1];
    const float* b1 = (const float*)d_in[2];
    const float* W2 = (const float*)d_in[3];
    const float* b2 = (const float*)d_in[4];
    const float* W3 = (const float*)d_in[5];
    const float* b3 = (const float*)d_in[6];
    float* out = (float*)d_out;
    (void)in_sizes; (void)n_in; (void)out_size;

    sort_kernel<<<BATCH, D>>>(x);
    softsort_kernel<<<dim3(D / 256, BATCH), 256>>>();
    gemm_fused_kernel<<<dim3(NTILES, KSPLIT), 256>>>(0, W1, b1);
    gemm_fused_kernel<<<dim3(NTILES, KSPLIT), 256>>>(1, W2, b2);
    final_kernel<<<BATCH, 256>>>(W3, b3, out);
}